// round 9
// baseline (speedup 1.0000x reference)
#include <cuda_runtime.h>

#define BB 32
#define OO 64
#define MM 128
#define HH 4
#define EE 64
#define HE 256
#define OBA 16        // o's per block, kernel A
#define OBB 4         // o's per block, kernel B
#define EP 68         // padded ctx row stride (floats) -> LDS.128 conflict-free
#define EP4 17        // EP/4

// scratch: raw logits [b][o][h][m] (4 MB)
__device__ float g_logits[(size_t)BB * OO * HH * MM];

__device__ __forceinline__ float tanh_approx(float x) {
    float r;
    asm("tanh.approx.f32 %0, %1;" : "=f"(r) : "f"(x));
    return r;
}

// ===================== Kernel A: q-proj + logits (MUFU-bound) =====================
// grid = 128 (b, og16), block = 512  -- UNCHANGED from R7 (at MUFU floor)
#define SMEM_A_FLOATS (MM*EP + OBA*HE + EE + OBA*EE)

__global__ __launch_bounds__(512, 1) void attnA_logits_kernel(
    const float* __restrict__ query,   // [B,O,E]
    const float* __restrict__ context, // [B,M,E]
    const float* __restrict__ W_ch,    // [E, HE]
    const float* __restrict__ b_ch,    // [HE]
    const float* __restrict__ w_logit) // [E]
{
    extern __shared__ float smem[];
    float* ctxS  = smem;                    // [MM][EP]
    float* qS    = ctxS + MM * EP;          // [OBA][HE]
    float* wS    = qS + OBA * HE;           // [EE]
    float* qrowS = wS + EE;                 // [OBA][EE]
    float4* ctxS4 = (float4*)ctxS;

    const int t  = threadIdx.x;
    const int b  = blockIdx.x >> 2;
    const int o0 = (blockIdx.x & 3) * OBA;

    // ---- stage ----
    const float4* ctxG4 = (const float4*)(context + (size_t)b * MM * EE);
    #pragma unroll
    for (int i = t; i < MM * EE / 4; i += 512) {
        int m = i >> 4, j = i & 15;
        ctxS4[m * EP4 + j] = ctxG4[i];
    }
    if (t < EE) wS[t] = w_logit[t];
    #pragma unroll
    for (int i = t; i < OBA * EE; i += 512)
        qrowS[i] = query[(size_t)(b * OO + o0) * EE + i];
    __syncthreads();

    // ---- q projection: thread=(grp,col), 8 o-accumulators ----
    {
        const int col = t & 255;
        const int grp = t >> 8;               // 0/1 -> o range grp*8..+7
        const float* qr = qrowS + grp * 8 * EE;
        float acc[8];
        float bc = b_ch[col];
        #pragma unroll
        for (int i = 0; i < 8; i++) acc[i] = bc;
        #pragma unroll 8
        for (int k = 0; k < EE; k++) {
            float w = W_ch[k * HE + col];
            #pragma unroll
            for (int i = 0; i < 8; i++)
                acc[i] = fmaf(qr[i * EE + k], w, acc[i]);
        }
        #pragma unroll
        for (int i = 0; i < 8; i++)
            qS[(grp * 8 + i) * HE + col] = acc[i];
    }
    __syncthreads();

    // ---- logits: thread=(h,m); 4 passes of 4 o's; raw logits to global ----
    {
        const int h = t >> 7;                 // warp-uniform
        const int m = t & 127;
        const float4* cr4 = ctxS4 + m * EP4;  // conflict-free LDS.128
        const float4* w4p = (const float4*)wS;
        float* gout = g_logits + (((size_t)(b * OO + o0) * HH + h) * MM) + m;
        const size_t ostride = (size_t)HH * MM;
        #pragma unroll
        for (int og = 0; og < 4; og++) {
            const float4* q0p = (const float4*)(qS + (og * 4 + 0) * HE) + h * 16;
            const float4* q1p = (const float4*)(qS + (og * 4 + 1) * HE) + h * 16;
            const float4* q2p = (const float4*)(qS + (og * 4 + 2) * HE) + h * 16;
            const float4* q3p = (const float4*)(qS + (og * 4 + 3) * HE) + h * 16;
            float a0 = 0.f, a1 = 0.f, a2 = 0.f, a3 = 0.f;
            #pragma unroll
            for (int j = 0; j < 16; j++) {
                float4 w4 = w4p[j];
                float4 c4 = cr4[j];
                float4 q0 = q0p[j], q1 = q1p[j], q2 = q2p[j], q3 = q3p[j];
                a0 = fmaf(w4.x, tanh_approx(c4.x + q0.x), a0);
                a1 = fmaf(w4.x, tanh_approx(c4.x + q1.x), a1);
                a2 = fmaf(w4.x, tanh_approx(c4.x + q2.x), a2);
                a3 = fmaf(w4.x, tanh_approx(c4.x + q3.x), a3);
                a0 = fmaf(w4.y, tanh_approx(c4.y + q0.y), a0);
                a1 = fmaf(w4.y, tanh_approx(c4.y + q1.y), a1);
                a2 = fmaf(w4.y, tanh_approx(c4.y + q2.y), a2);
                a3 = fmaf(w4.y, tanh_approx(c4.y + q3.y), a3);
                a0 = fmaf(w4.z, tanh_approx(c4.z + q0.z), a0);
                a1 = fmaf(w4.z, tanh_approx(c4.z + q1.z), a1);
                a2 = fmaf(w4.z, tanh_approx(c4.z + q2.z), a2);
                a3 = fmaf(w4.z, tanh_approx(c4.z + q3.z), a3);
                a0 = fmaf(w4.w, tanh_approx(c4.w + q0.w), a0);
                a1 = fmaf(w4.w, tanh_approx(c4.w + q1.w), a1);
                a2 = fmaf(w4.w, tanh_approx(c4.w + q2.w), a2);
                a3 = fmaf(w4.w, tanh_approx(c4.w + q3.w), a3);
            }
            gout[(og * 4 + 0) * ostride] = a0;
            gout[(og * 4 + 1) * ostride] = a1;
            gout[(og * 4 + 2) * ostride] = a2;
            gout[(og * 4 + 3) * ostride] = a3;
        }
    }
}

// ===================== Kernel B: softmax + heads + out GEMM (one wave) =============
// grid = 512 (b, og4), block = 256, 4 blocks/SM resident -> whole grid in 1 wave
// smem: memS[MM][EE]=8192 | probS[16][MM]=2048 (reused as redS) | headsS[OBB*HE]=1024
#define SMEM_B_FLOATS (MM*EE + (OBB*HH)*MM + OBB*HE)

__global__ __launch_bounds__(256, 4) void attnB_out_kernel(
    const float* __restrict__ memory,  // [B,M,E]
    const float* __restrict__ W_rh,    // [HE, E]
    const float* __restrict__ b_rh,    // [E]
    const float* __restrict__ temp,    // [1]
    float* __restrict__ out)           // [B,O,E]
{
    extern __shared__ float smem[];
    float* memS   = smem;                  // [MM][EE]
    float* probS  = memS + MM * EE;        // [16 rows][MM]; later redS[4][256]
    float* headsS = probS + 16 * MM;       // [OBB][HE] flat: o*256 + h*64 + e
    float4* memS4 = (float4*)memS;

    const int t  = threadIdx.x;
    const int b  = blockIdx.x >> 4;
    const int o0 = (blockIdx.x & 15) * OBB;

    // ---- stage memory tile (L2-resident) ----
    const float4* memG4 = (const float4*)(memory + (size_t)b * MM * EE);
    #pragma unroll
    for (int i = t; i < MM * EE / 4; i += 256)
        memS4[i] = memG4[i];

    // ---- softmax: 8 warps x 2 rows; row = o_local*HH + h ----
    {
        const float invtemp = 1.0f / temp[0];
        const int warp = t >> 5, lane = t & 31;
        #pragma unroll
        for (int rr = 0; rr < 2; rr++) {
            const int r = warp * 2 + rr;             // 0..15
            const int ol = r >> 2, h = r & 3;
            const float4* lg = (const float4*)(g_logits +
                (((size_t)(b * OO + o0 + ol) * HH + h) * MM));
            float4 v = lg[lane];
            float mx = fmaxf(fmaxf(v.x, v.y), fmaxf(v.z, v.w));
            #pragma unroll
            for (int s = 16; s; s >>= 1)
                mx = fmaxf(mx, __shfl_xor_sync(0xFFFFFFFFu, mx, s));
            float e0 = __expf((v.x - mx) * invtemp);
            float e1 = __expf((v.y - mx) * invtemp);
            float e2 = __expf((v.z - mx) * invtemp);
            float e3 = __expf((v.w - mx) * invtemp);
            float sm = e0 + e1 + e2 + e3;
            #pragma unroll
            for (int s = 16; s; s >>= 1)
                sm += __shfl_xor_sync(0xFFFFFFFFu, sm, s);
            float inv = 1.0f / sm;
            ((float4*)(probS + r * MM))[lane] =
                make_float4(e0 * inv, e1 * inv, e2 * inv, e3 * inv);
        }
    }
    __syncthreads();

    // ---- heads GEMM: 16 rows x 16 fl4-cols, exactly 1 per thread ----
    {
        const int r  = t >> 4;                 // 0..15 = o_local*4 + h
        const int ct = t & 15;                 // float4 column
        const float*  pr = probS + r * MM;
        const float4* mv = memS4 + ct;
        float4 A = make_float4(0.f, 0.f, 0.f, 0.f);
        #pragma unroll 8
        for (int m = 0; m < MM; m++) {
            float  p = pr[m];                  // broadcast (r uniform per 16 lanes)
            float4 v = mv[m * 16];
            A.x = fmaf(p, v.x, A.x); A.y = fmaf(p, v.y, A.y);
            A.z = fmaf(p, v.z, A.z); A.w = fmaf(p, v.w, A.w);
        }
        float4 H;
        H.x = (A.x > 0.f) ? A.x : 0.01f * A.x;
        H.y = (A.y > 0.f) ? A.y : 0.01f * A.y;
        H.z = (A.z > 0.f) ? A.z : 0.01f * A.z;
        H.w = (A.w > 0.f) ? A.w : 0.01f * A.w;
        ((float4*)headsS)[t] = H;              // headsS[o][h*64+4*ct+c] (r*16+ct)
    }
    __syncthreads();

    // ---- out GEMM: thread=(k-part,e); W_rh read ONCE per block; 4 o-accums ----
    float* redS = probS;                       // reuse [4 parts][256]
    {
        const int part = t >> 6;               // 0..3 -> k range part*64..+63
        const int e    = t & 63;
        const float* wr = W_rh + (part * 64) * EE + e;
        const float* hs = headsS + part * 64;
        float a0 = 0.f, a1 = 0.f, a2 = 0.f, a3 = 0.f;
        #pragma unroll 8
        for (int k = 0; k < 64; k++) {
            float w = wr[k * EE];              // coalesced LDG (L2)
            a0 = fmaf(hs[0 * HE + k], w, a0);  // warp-uniform smem broadcast
            a1 = fmaf(hs[1 * HE + k], w, a1);
            a2 = fmaf(hs[2 * HE + k], w, a2);
            a3 = fmaf(hs[3 * HE + k], w, a3);
        }
        float* rd = redS + part * 256 + e;
        rd[0]   = a0;
        rd[64]  = a1;
        rd[128] = a2;
        rd[192] = a3;
    }
    __syncthreads();
    {
        const int o = t >> 6, e = t & 63;      // t = o*64+e, 256 outputs
        float v = b_rh[e]
                + redS[t] + redS[256 + t] + redS[512 + t] + redS[768 + t];
        out[(size_t)(b * OO + o0 + o) * EE + e] = v;
    }
}

extern "C" void kernel_launch(void* const* d_in, const int* in_sizes, int n_in,
                              void* d_out, int out_size) {
    const float* query   = (const float*)d_in[0];
    const float* context = (const float*)d_in[1];
    const float* memory  = (const float*)d_in[2];
    const float* W_ch    = (const float*)d_in[3];
    const float* b_ch    = (const float*)d_in[4];
    const float* w_logit = (const float*)d_in[5];
    const float* W_rh    = (const float*)d_in[7];
    const float* b_rh    = (const float*)d_in[8];
    const float* temp    = (const float*)d_in[9];
    float* out = (float*)d_out;

    const size_t smemA = SMEM_A_FLOATS * sizeof(float);
    const size_t smemB = SMEM_B_FLOATS * sizeof(float);
    cudaFuncSetAttribute(attnA_logits_kernel,
                         cudaFuncAttributeMaxDynamicSharedMemorySize, (int)smemA);
    cudaFuncSetAttribute(attnB_out_kernel,
                         cudaFuncAttributeMaxDynamicSharedMemorySize, (int)smemB);

    attnA_logits_kernel<<<BB * (OO / OBA), 512, smemA>>>(
        query, context, W_ch, b_ch, w_logit);
    attnB_out_kernel<<<BB * (OO / OBB), 256, smemB>>>(
        memory, W_rh, b_rh, temp, out);
}

// round 10
// speedup vs baseline: 1.1577x; 1.1577x over previous
#include <cuda_runtime.h>

#define BB 32
#define OO 64
#define MM 128
#define HH 4
#define EE 64
#define HE 256
#define OBA 16        // o's per block, kernel A
#define OBB 4         // o's per block, kernel B
#define EP 68         // padded ctx row stride (floats) -> LDS.128 conflict-free
#define EP4 17        // EP/4
#define PP 132        // probS row stride (floats): mult-of-4, bank-skewed

// scratch: raw logits [b][o][h][m] (4 MB)
__device__ float g_logits[(size_t)BB * OO * HH * MM];

__device__ __forceinline__ float tanh_approx(float x) {
    float r;
    asm("tanh.approx.f32 %0, %1;" : "=f"(r) : "f"(x));
    return r;
}

// ===================== Kernel A: q-proj + logits (MUFU-bound) =====================
// grid = 128 (b, og16), block = 512  -- UNCHANGED (at MUFU floor for this grid)
#define SMEM_A_FLOATS (MM*EP + OBA*HE + EE + OBA*EE)

__global__ __launch_bounds__(512, 1) void attnA_logits_kernel(
    const float* __restrict__ query,   // [B,O,E]
    const float* __restrict__ context, // [B,M,E]
    const float* __restrict__ W_ch,    // [E, HE]
    const float* __restrict__ b_ch,    // [HE]
    const float* __restrict__ w_logit) // [E]
{
    extern __shared__ float smem[];
    float* ctxS  = smem;                    // [MM][EP]
    float* qS    = ctxS + MM * EP;          // [OBA][HE]
    float* wS    = qS + OBA * HE;           // [EE]
    float* qrowS = wS + EE;                 // [OBA][EE]
    float4* ctxS4 = (float4*)ctxS;

    const int t  = threadIdx.x;
    const int b  = blockIdx.x >> 2;
    const int o0 = (blockIdx.x & 3) * OBA;

    const float4* ctxG4 = (const float4*)(context + (size_t)b * MM * EE);
    #pragma unroll
    for (int i = t; i < MM * EE / 4; i += 512) {
        int m = i >> 4, j = i & 15;
        ctxS4[m * EP4 + j] = ctxG4[i];
    }
    if (t < EE) wS[t] = w_logit[t];
    #pragma unroll
    for (int i = t; i < OBA * EE; i += 512)
        qrowS[i] = query[(size_t)(b * OO + o0) * EE + i];
    __syncthreads();

    {
        const int col = t & 255;
        const int grp = t >> 8;
        const float* qr = qrowS + grp * 8 * EE;
        float acc[8];
        float bc = b_ch[col];
        #pragma unroll
        for (int i = 0; i < 8; i++) acc[i] = bc;
        #pragma unroll 8
        for (int k = 0; k < EE; k++) {
            float w = W_ch[k * HE + col];
            #pragma unroll
            for (int i = 0; i < 8; i++)
                acc[i] = fmaf(qr[i * EE + k], w, acc[i]);
        }
        #pragma unroll
        for (int i = 0; i < 8; i++)
            qS[(grp * 8 + i) * HE + col] = acc[i];
    }
    __syncthreads();

    {
        const int h = t >> 7;
        const int m = t & 127;
        const float4* cr4 = ctxS4 + m * EP4;
        const float4* w4p = (const float4*)wS;
        float* gout = g_logits + (((size_t)(b * OO + o0) * HH + h) * MM) + m;
        const size_t ostride = (size_t)HH * MM;
        #pragma unroll
        for (int og = 0; og < 4; og++) {
            const float4* q0p = (const float4*)(qS + (og * 4 + 0) * HE) + h * 16;
            const float4* q1p = (const float4*)(qS + (og * 4 + 1) * HE) + h * 16;
            const float4* q2p = (const float4*)(qS + (og * 4 + 2) * HE) + h * 16;
            const float4* q3p = (const float4*)(qS + (og * 4 + 3) * HE) + h * 16;
            float a0 = 0.f, a1 = 0.f, a2 = 0.f, a3 = 0.f;
            #pragma unroll
            for (int j = 0; j < 16; j++) {
                float4 w4 = w4p[j];
                float4 c4 = cr4[j];
                float4 q0 = q0p[j], q1 = q1p[j], q2 = q2p[j], q3 = q3p[j];
                a0 = fmaf(w4.x, tanh_approx(c4.x + q0.x), a0);
                a1 = fmaf(w4.x, tanh_approx(c4.x + q1.x), a1);
                a2 = fmaf(w4.x, tanh_approx(c4.x + q2.x), a2);
                a3 = fmaf(w4.x, tanh_approx(c4.x + q3.x), a3);
                a0 = fmaf(w4.y, tanh_approx(c4.y + q0.y), a0);
                a1 = fmaf(w4.y, tanh_approx(c4.y + q1.y), a1);
                a2 = fmaf(w4.y, tanh_approx(c4.y + q2.y), a2);
                a3 = fmaf(w4.y, tanh_approx(c4.y + q3.y), a3);
                a0 = fmaf(w4.z, tanh_approx(c4.z + q0.z), a0);
                a1 = fmaf(w4.z, tanh_approx(c4.z + q1.z), a1);
                a2 = fmaf(w4.z, tanh_approx(c4.z + q2.z), a2);
                a3 = fmaf(w4.z, tanh_approx(c4.z + q3.z), a3);
                a0 = fmaf(w4.w, tanh_approx(c4.w + q0.w), a0);
                a1 = fmaf(w4.w, tanh_approx(c4.w + q1.w), a1);
                a2 = fmaf(w4.w, tanh_approx(c4.w + q2.w), a2);
                a3 = fmaf(w4.w, tanh_approx(c4.w + q3.w), a3);
            }
            gout[(og * 4 + 0) * ostride] = a0;
            gout[(og * 4 + 1) * ostride] = a1;
            gout[(og * 4 + 2) * ostride] = a2;
            gout[(og * 4 + 3) * ostride] = a3;
        }
    }
}

// ===================== Kernel B: softmax + heads + out (LDS-lean) ==================
// grid = 512 (b, og4), block = 256
// smem floats: memS[MM][EE]=8192 | probS[16][PP]=2112 | headsS[OBB*HE]=1024  (45.3KB)
// memS region is re-aliased (after syncs) as reduction scratch in heads & out phases.
#define SMEM_B_FLOATS (MM*EE + (OBB*HH)*PP + OBB*HE)

__global__ __launch_bounds__(256, 4) void attnB_out_kernel(
    const float* __restrict__ memory,  // [B,M,E]
    const float* __restrict__ W_rh,    // [HE, E]
    const float* __restrict__ b_rh,    // [E]
    const float* __restrict__ temp,    // [1]
    float* __restrict__ out)           // [B,O,E]
{
    extern __shared__ float smem[];
    float* memS   = smem;                  // [MM][EE]
    float* probS  = memS + MM * EE;        // [16][PP]
    float* headsS = probS + 16 * PP;       // [OBB][HE] flat: o*256 + h*64 + e
    float4* memS4 = (float4*)memS;

    const int t  = threadIdx.x;
    const int b  = blockIdx.x >> 4;
    const int o0 = (blockIdx.x & 15) * OBB;

    // ---- stage memory tile ----
    const float4* memG4 = (const float4*)(memory + (size_t)b * MM * EE);
    #pragma unroll
    for (int i = t; i < MM * EE / 4; i += 256)
        memS4[i] = memG4[i];

    // ---- softmax: 8 warps x 2 rows; row r = o_local*HH + h ----
    {
        const float invtemp = 1.0f / temp[0];
        const int warp = t >> 5, lane = t & 31;
        #pragma unroll
        for (int rr = 0; rr < 2; rr++) {
            const int r = warp * 2 + rr;             // 0..15
            const int ol = r >> 2, h = r & 3;
            const float4* lg = (const float4*)(g_logits +
                (((size_t)(b * OO + o0 + ol) * HH + h) * MM));
            float4 v = lg[lane];
            float mx = fmaxf(fmaxf(v.x, v.y), fmaxf(v.z, v.w));
            #pragma unroll
            for (int s = 16; s; s >>= 1)
                mx = fmaxf(mx, __shfl_xor_sync(0xFFFFFFFFu, mx, s));
            float e0 = __expf((v.x - mx) * invtemp);
            float e1 = __expf((v.y - mx) * invtemp);
            float e2 = __expf((v.z - mx) * invtemp);
            float e3 = __expf((v.w - mx) * invtemp);
            float sm = e0 + e1 + e2 + e3;
            #pragma unroll
            for (int s = 16; s; s >>= 1)
                sm += __shfl_xor_sync(0xFFFFFFFFu, sm, s);
            float inv = 1.0f / sm;
            ((float4*)(probS + r * PP))[lane] =
                make_float4(e0 * inv, e1 * inv, e2 * inv, e3 * inv);
        }
    }
    __syncthreads();

    // ---- heads GEMM with o-register-tiling: thread=(mpart,h,ct), 4 o-accums ----
    {
        const int mpart = t >> 6;              // 0..3 -> m range mpart*32..+31
        const int h     = (t >> 4) & 3;
        const int ct    = t & 15;              // float4 column
        const float4* mv = memS4 + ct;
        const float* p0 = probS + (0 * 4 + h) * PP;
        const float* p1 = probS + (1 * 4 + h) * PP;
        const float* p2 = probS + (2 * 4 + h) * PP;
        const float* p3 = probS + (3 * 4 + h) * PP;
        float4 A0 = make_float4(0.f,0.f,0.f,0.f);
        float4 A1 = make_float4(0.f,0.f,0.f,0.f);
        float4 A2 = make_float4(0.f,0.f,0.f,0.f);
        float4 A3 = make_float4(0.f,0.f,0.f,0.f);
        const int m0 = mpart * 32;
        #pragma unroll 4
        for (int m = m0; m < m0 + 32; m++) {
            float4 v = mv[m * 16];             // 1 LDS.128 feeds 16 FMA
            float a = p0[m], c = p1[m], d = p2[m], f = p3[m];
            A0.x = fmaf(a, v.x, A0.x); A0.y = fmaf(a, v.y, A0.y);
            A0.z = fmaf(a, v.z, A0.z); A0.w = fmaf(a, v.w, A0.w);
            A1.x = fmaf(c, v.x, A1.x); A1.y = fmaf(c, v.y, A1.y);
            A1.z = fmaf(c, v.z, A1.z); A1.w = fmaf(c, v.w, A1.w);
            A2.x = fmaf(d, v.x, A2.x); A2.y = fmaf(d, v.y, A2.y);
            A2.z = fmaf(d, v.z, A2.z); A2.w = fmaf(d, v.w, A2.w);
            A3.x = fmaf(f, v.x, A3.x); A3.y = fmaf(f, v.y, A3.y);
            A3.z = fmaf(f, v.z, A3.z); A3.w = fmaf(f, v.w, A3.w);
        }
        __syncthreads();                       // memS reads done -> safe to alias
        float* redS = memS;                    // [4 mpart][16 rows][64 e]
        float4* rd = (float4*)(redS + mpart * 1024 + h * 64);
        rd[ct]            = A0;                // row = 0*4+h
        rd[ct + 4 * 16]   = A1;                // row = 1*4+h  (+256 floats = 64 fl4)
        rd[ct + 8 * 16]   = A2;
        rd[ct + 12 * 16]  = A3;
    }
    __syncthreads();

    // ---- reduce 4 m-partials -> heads + leaky relu ----
    {
        const float* redS = memS;
        const int r  = t >> 4;                 // 0..15 = o*4+h
        const int ct = t & 15;
        const float4* r0 = (const float4*)(redS + r * 64) + ct;
        float4 s0 = r0[0];
        float4 s1 = r0[256];                   // +1024 floats = 256 fl4
        float4 s2 = r0[512];
        float4 s3 = r0[768];
        float4 A;
        A.x = (s0.x + s1.x) + (s2.x + s3.x);
        A.y = (s0.y + s1.y) + (s2.y + s3.y);
        A.z = (s0.z + s1.z) + (s2.z + s3.z);
        A.w = (s0.w + s1.w) + (s2.w + s3.w);
        float4 H;
        H.x = (A.x > 0.f) ? A.x : 0.01f * A.x;
        H.y = (A.y > 0.f) ? A.y : 0.01f * A.y;
        H.z = (A.z > 0.f) ? A.z : 0.01f * A.z;
        H.w = (A.w > 0.f) ? A.w : 0.01f * A.w;
        ((float4*)(headsS + (r >> 2) * HE + (r & 3) * 64))[ct] = H;
    }
    __syncthreads();

    // ---- out GEMM: thread=(k-part,e); W_rh read ONCE per block; 4 o-accums ----
    {
        const int part = t >> 6;               // 0..3 -> k range part*64..+63
        const int e    = t & 63;
        const float* wr = W_rh + (part * 64) * EE + e;
        const float* hs = headsS + part * 64;
        float a0 = 0.f, a1 = 0.f, a2 = 0.f, a3 = 0.f;
        #pragma unroll 8
        for (int k = 0; k < 64; k++) {
            float w = wr[k * EE];              // coalesced LDG (L2)
            a0 = fmaf(hs[0 * HE + k], w, a0);  // warp-uniform smem broadcast
            a1 = fmaf(hs[1 * HE + k], w, a1);
            a2 = fmaf(hs[2 * HE + k], w, a2);
            a3 = fmaf(hs[3 * HE + k], w, a3);
        }
        float* redS = memS;                    // reuse again: [4 part][4 o][64 e]
        float* rd = redS + part * 256 + e;
        rd[0]   = a0;
        rd[64]  = a1;
        rd[128] = a2;
        rd[192] = a3;
    }
    __syncthreads();
    {
        const float* redS = memS;
        const int o = t >> 6, e = t & 63;      // t = o*64+e, 256 outputs
        float v = b_rh[e]
                + redS[t] + redS[256 + t] + redS[512 + t] + redS[768 + t];
        out[(size_t)(b * OO + o0 + o) * EE + e] = v;
    }
}

extern "C" void kernel_launch(void* const* d_in, const int* in_sizes, int n_in,
                              void* d_out, int out_size) {
    const float* query   = (const float*)d_in[0];
    const float* context = (const float*)d_in[1];
    const float* memory  = (const float*)d_in[2];
    const float* W_ch    = (const float*)d_in[3];
    const float* b_ch    = (const float*)d_in[4];
    const float* w_logit = (const float*)d_in[5];
    const float* W_rh    = (const float*)d_in[7];
    const float* b_rh    = (const float*)d_in[8];
    const float* temp    = (const float*)d_in[9];
    float* out = (float*)d_out;

    const size_t smemA = SMEM_A_FLOATS * sizeof(float);
    const size_t smemB = SMEM_B_FLOATS * sizeof(float);
    cudaFuncSetAttribute(attnA_logits_kernel,
                         cudaFuncAttributeMaxDynamicSharedMemorySize, (int)smemA);
    cudaFuncSetAttribute(attnB_out_kernel,
                         cudaFuncAttributeMaxDynamicSharedMemorySize, (int)smemB);

    attnA_logits_kernel<<<BB * (OO / OBA), 512, smemA>>>(
        query, context, W_ch, b_ch, w_logit);
    attnB_out_kernel<<<BB * (OO / OBB), 256, smemB>>>(
        memory, W_rh, b_rh, temp, out);
}

// round 12
// speedup vs baseline: 1.2312x; 1.0635x over previous
#include <cuda_runtime.h>

#define BB 32
#define OO 64
#define MM 128
#define HH 4
#define EE 64
#define HE 256
#define OB 4          // o's per block
#define EP 68         // padded ctx row stride (floats) -> LDS.128 conflict-free
#define EP4 17        // EP/4
#define PP 132        // probS row stride (floats)

__device__ __forceinline__ float tanh_approx(float x) {
    float r;
    asm("tanh.approx.f32 %0, %1;" : "=f"(r) : "f"(x));
    return r;
}

// smem floats:
//  ctxS [MM][EP]  = 8704
//  memS [MM][EE]  = 8192  (aliased as reduction scratch after heads-phase reads)
//  qS   [OB][HE]  = 1024
//  wS   [EE]      = 64
//  qrowS[OB][EE]  = 256
//  probS[16][PP]  = 2112  (logits -> probs in place)
//  headsS[OB][HE] = 1024
// total 21376 fl = 85.5 KB -> 2 blocks/SM = 171 KB
#define SMEM_FLOATS (MM*EP + MM*EE + OB*HE + EE + OB*EE + 16*PP + OB*HE)

__global__ __launch_bounds__(512, 2) void attn_fused4_kernel(
    const float* __restrict__ query,   // [B,O,E]
    const float* __restrict__ context, // [B,M,E]
    const float* __restrict__ memory,  // [B,M,E]
    const float* __restrict__ W_ch,    // [E, HE]
    const float* __restrict__ b_ch,    // [HE]
    const float* __restrict__ w_logit, // [E]
    const float* __restrict__ W_rh,    // [HE, E]
    const float* __restrict__ b_rh,    // [E]
    const float* __restrict__ temp,    // [1]
    float* __restrict__ out)           // [B,O,E]
{
    extern __shared__ float smem[];
    float* ctxS   = smem;                    // [MM][EP]
    float* memS   = ctxS + MM * EP;          // [MM][EE]
    float* qS     = memS + MM * EE;          // [OB][HE]
    float* wS     = qS + OB * HE;            // [EE]
    float* qrowS  = wS + EE;                 // [OB][EE]
    float* probS  = qrowS + OB * EE;         // [16][PP]
    float* headsS = probS + 16 * PP;         // [OB][HE]
    float4* ctxS4 = (float4*)ctxS;
    float4* memS4 = (float4*)memS;

    const int t  = threadIdx.x;
    const int b  = blockIdx.x >> 4;
    const int o0 = (blockIdx.x & 15) * OB;

    // ---- stage ----
    const float4* ctxG4 = (const float4*)(context + (size_t)b * MM * EE);
    const float4* memG4 = (const float4*)(memory  + (size_t)b * MM * EE);
    #pragma unroll
    for (int i = t; i < MM * EE / 4; i += 512) {
        int m = i >> 4, j = i & 15;
        ctxS4[m * EP4 + j] = ctxG4[i];
        memS4[i]           = memG4[i];
    }
    if (t < EE) wS[t] = w_logit[t];
    if (t < OB * EE)
        qrowS[t] = query[(size_t)(b * OO + o0) * EE + t];
    __syncthreads();

    // ---- q projection: thread=(grp2,col256), 2 o-accums ----
    {
        const int col = t & 255;
        const int grp = t >> 8;               // o pair grp*2, grp*2+1
        const float* qr = qrowS + grp * 2 * EE;
        float bc = b_ch[col];
        float a0 = bc, a1 = bc;
        #pragma unroll 8
        for (int k = 0; k < EE; k++) {
            float w = W_ch[k * HE + col];
            a0 = fmaf(qr[k],      w, a0);
            a1 = fmaf(qr[EE + k], w, a1);
        }
        qS[(grp * 2 + 0) * HE + col] = a0;
        qS[(grp * 2 + 1) * HE + col] = a1;
    }
    __syncthreads();

    // ---- logits -> probS rows r = o*HH + h ----
    {
        const int h = t >> 7;                 // warp-uniform
        const int m = t & 127;
        const float4* cr4 = ctxS4 + m * EP4;  // conflict-free LDS.128
        const float4* w4p = (const float4*)wS;
        const float4* q0p = (const float4*)(qS + 0 * HE) + h * 16;
        const float4* q1p = (const float4*)(qS + 1 * HE) + h * 16;
        const float4* q2p = (const float4*)(qS + 2 * HE) + h * 16;
        const float4* q3p = (const float4*)(qS + 3 * HE) + h * 16;
        float a0 = 0.f, a1 = 0.f, a2 = 0.f, a3 = 0.f;
        #pragma unroll
        for (int j = 0; j < 16; j++) {
            float4 w4 = w4p[j];
            float4 c4 = cr4[j];
            float4 q0 = q0p[j], q1 = q1p[j], q2 = q2p[j], q3 = q3p[j];
            a0 = fmaf(w4.x, tanh_approx(c4.x + q0.x), a0);
            a1 = fmaf(w4.x, tanh_approx(c4.x + q1.x), a1);
            a2 = fmaf(w4.x, tanh_approx(c4.x + q2.x), a2);
            a3 = fmaf(w4.x, tanh_approx(c4.x + q3.x), a3);
            a0 = fmaf(w4.y, tanh_approx(c4.y + q0.y), a0);
            a1 = fmaf(w4.y, tanh_approx(c4.y + q1.y), a1);
            a2 = fmaf(w4.y, tanh_approx(c4.y + q2.y), a2);
            a3 = fmaf(w4.y, tanh_approx(c4.y + q3.y), a3);
            a0 = fmaf(w4.z, tanh_approx(c4.z + q0.z), a0);
            a1 = fmaf(w4.z, tanh_approx(c4.z + q1.z), a1);
            a2 = fmaf(w4.z, tanh_approx(c4.z + q2.z), a2);
            a3 = fmaf(w4.z, tanh_approx(c4.z + q3.z), a3);
            a0 = fmaf(w4.w, tanh_approx(c4.w + q0.w), a0);
            a1 = fmaf(w4.w, tanh_approx(c4.w + q1.w), a1);
            a2 = fmaf(w4.w, tanh_approx(c4.w + q2.w), a2);
            a3 = fmaf(w4.w, tanh_approx(c4.w + q3.w), a3);
        }
        probS[(0 * HH + h) * PP + m] = a0;
        probS[(1 * HH + h) * PP + m] = a1;
        probS[(2 * HH + h) * PP + m] = a2;
        probS[(3 * HH + h) * PP + m] = a3;
    }
    __syncthreads();

    // ---- softmax: 16 warps x 1 row (r = o*HH + h); temp applied here ----
    {
        const float invtemp = 1.0f / temp[0];
        const int warp = t >> 5, lane = t & 31;
        float4* L = (float4*)(probS + warp * PP);
        float4 v = L[lane];
        float mx = fmaxf(fmaxf(v.x, v.y), fmaxf(v.z, v.w));
        #pragma unroll
        for (int s = 16; s; s >>= 1)
            mx = fmaxf(mx, __shfl_xor_sync(0xFFFFFFFFu, mx, s));
        float e0 = __expf((v.x - mx) * invtemp);
        float e1 = __expf((v.y - mx) * invtemp);
        float e2 = __expf((v.z - mx) * invtemp);
        float e3 = __expf((v.w - mx) * invtemp);
        float sm = e0 + e1 + e2 + e3;
        #pragma unroll
        for (int s = 16; s; s >>= 1)
            sm += __shfl_xor_sync(0xFFFFFFFFu, sm, s);
        float inv = 1.0f / sm;
        L[lane] = make_float4(e0 * inv, e1 * inv, e2 * inv, e3 * inv);
    }
    __syncthreads();

    // ---- heads GEMM, o-register-tiled: thread=(mpart8,h4,ct16), 4 o-accums ----
    {
        const int mpart = t >> 6;              // 0..7 -> m range mpart*16..+15
        const int h     = (t >> 4) & 3;
        const int ct    = t & 15;
        const float4* mv = memS4 + ct;
        const float* p0 = probS + (0 * HH + h) * PP;
        const float* p1 = probS + (1 * HH + h) * PP;
        const float* p2 = probS + (2 * HH + h) * PP;
        const float* p3 = probS + (3 * HH + h) * PP;
        float4 A0 = make_float4(0.f,0.f,0.f,0.f);
        float4 A1 = make_float4(0.f,0.f,0.f,0.f);
        float4 A2 = make_float4(0.f,0.f,0.f,0.f);
        float4 A3 = make_float4(0.f,0.f,0.f,0.f);
        const int m0 = mpart * 16;
        #pragma unroll 4
        for (int m = m0; m < m0 + 16; m++) {
            float4 v = mv[m * 16];             // 1 LDS.128 feeds 16 FMA
            float a = p0[m], c = p1[m], d = p2[m], f = p3[m];
            A0.x = fmaf(a, v.x, A0.x); A0.y = fmaf(a, v.y, A0.y);
            A0.z = fmaf(a, v.z, A0.z); A0.w = fmaf(a, v.w, A0.w);
            A1.x = fmaf(c, v.x, A1.x); A1.y = fmaf(c, v.y, A1.y);
            A1.z = fmaf(c, v.z, A1.z); A1.w = fmaf(c, v.w, A1.w);
            A2.x = fmaf(d, v.x, A2.x); A2.y = fmaf(d, v.y, A2.y);
            A2.z = fmaf(d, v.z, A2.z); A2.w = fmaf(d, v.w, A2.w);
            A3.x = fmaf(f, v.x, A3.x); A3.y = fmaf(f, v.y, A3.y);
            A3.z = fmaf(f, v.z, A3.z); A3.w = fmaf(f, v.w, A3.w);
        }
        __syncthreads();                       // all memS reads done -> alias safe
        float* redS = memS;                    // [8 mpart][16 r][64 e]
        float4* rd = (float4*)(redS + mpart * 1024 + h * 64);
        rd[ct]           = A0;                 // r = 0*4+h
        rd[ct + 64]      = A1;                 // r = 1*4+h  (+256 fl)
        rd[ct + 128]     = A2;
        rd[ct + 192]     = A3;
    }
    __syncthreads();

    // ---- reduce 8 m-partials -> heads + leaky relu (256 threads) ----
    if (t < 256) {
        const float* redS = memS;
        const int r  = t >> 4;                 // 0..15 = o*4+h
        const int ct = t & 15;
        const float4* r0 = (const float4*)(redS + r * 64) + ct;
        float4 A = make_float4(0.f,0.f,0.f,0.f);
        #pragma unroll
        for (int p = 0; p < 8; p++) {
            float4 s = r0[p * 256];            // +1024 fl per partial
            A.x += s.x; A.y += s.y; A.z += s.z; A.w += s.w;
        }
        float4 H;
        H.x = (A.x > 0.f) ? A.x : 0.01f * A.x;
        H.y = (A.y > 0.f) ? A.y : 0.01f * A.y;
        H.z = (A.z > 0.f) ? A.z : 0.01f * A.z;
        H.w = (A.w > 0.f) ? A.w : 0.01f * A.w;
        ((float4*)(headsS + (r >> 2) * HE + (r & 3) * 64))[ct] = H;
    }
    __syncthreads();

    // ---- out GEMM: thread=(kpart8,e); W_rh read ONCE per block; 4 o-accums ----
    {
        const int part = t >> 6;               // 0..7 -> k range part*32..+31
        const int e    = t & 63;
        const float* wr = W_rh + (part * 32) * EE + e;
        const float* hs = headsS + part * 32;
        float a0 = 0.f, a1 = 0.f, a2 = 0.f, a3 = 0.f;
        #pragma unroll 8
        for (int k = 0; k < 32; k++) {
            float w = wr[k * EE];              // coalesced LDG (L2)
            a0 = fmaf(hs[0 * HE + k], w, a0);  // warp-uniform smem broadcast
            a1 = fmaf(hs[1 * HE + k], w, a1);
            a2 = fmaf(hs[2 * HE + k], w, a2);
            a3 = fmaf(hs[3 * HE + k], w, a3);
        }
        float* redS = memS;                    // [8 part][4 o][64 e]
        float* rd = redS + part * 256 + e;
        rd[0]   = a0;
        rd[64]  = a1;
        rd[128] = a2;
        rd[192] = a3;
    }
    __syncthreads();
    if (t < 256) {
        const float* redS = memS;
        const int o = t >> 6, e = t & 63;
        float v = b_rh[e];
        #pragma unroll
        for (int p = 0; p < 8; p++)
            v += redS[p * 256 + t];
        out[(size_t)(b * OO + o0 + o) * EE + e] = v;
    }
}

extern "C" void kernel_launch(void* const* d_in, const int* in_sizes, int n_in,
                              void* d_out, int out_size) {
    const float* query   = (const float*)d_in[0];
    const float* context = (const float*)d_in[1];
    const float* memory  = (const float*)d_in[2];
    const float* W_ch    = (const float*)d_in[3];
    const float* b_ch    = (const float*)d_in[4];
    const float* w_logit = (const float*)d_in[5];
    const float* W_rh    = (const float*)d_in[7];
    const float* b_rh    = (const float*)d_in[8];
    const float* temp    = (const float*)d_in[9];
    float* out = (float*)d_out;

    const size_t smem_bytes = SMEM_FLOATS * sizeof(float);
    cudaFuncSetAttribute(attn_fused4_kernel,
                         cudaFuncAttributeMaxDynamicSharedMemorySize,
                         (int)smem_bytes);

    attn_fused4_kernel<<<BB * (OO / OB), 512, smem_bytes>>>(
        query, context, memory, W_ch, b_ch, w_logit, W_rh, b_rh, temp, out);
}